// round 10
// baseline (speedup 1.0000x reference)
#include <cuda_runtime.h>
#include <cuda_bf16.h>

using u64 = unsigned long long;

__device__ __forceinline__ void fma2(u64& d, u64 a, u64 b) {
    asm("fma.rn.f32x2 %0, %1, %2, %0;" : "+l"(d) : "l"(a), "l"(b));
}
__device__ __forceinline__ u64 fma2n(u64 a, u64 b, u64 c) {
    u64 d;
    asm("fma.rn.f32x2 %0, %1, %2, %3;" : "=l"(d) : "l"(a), "l"(b), "l"(c));
    return d;
}
__device__ __forceinline__ u64 pack2(float x, float y) {
    u64 d;
    asm("mov.b64 %0, {%1, %2};" : "=l"(d) : "f"(x), "f"(y));
    return d;
}
__device__ __forceinline__ void unpack2(u64 v, float& x, float& y) {
    asm("mov.b64 {%0, %1}, %2;" : "=f"(x), "=f"(y) : "l"(v));
}
__device__ __forceinline__ void cp_async16(void* smem, const void* gmem) {
    unsigned s = (unsigned)__cvta_generic_to_shared(smem);
    asm volatile("cp.async.cg.shared.global [%0], [%1], 16;" :: "r"(s), "l"(gmem));
}
__device__ __forceinline__ void cp_commit() {
    asm volatile("cp.async.commit_group;");
}
template <int N>
__device__ __forceinline__ void cp_wait() {
    asm volatile("cp.async.wait_group %0;" :: "n"(N));
}

constexpr int TILE = 256;   // rows per tile (== blockDim.x)
constexpr int WARPS = 8;

// Core per-row computation.
// sPtI[j][2i+m] = -P_m[i][j]  (NEGATED + interleaved, 24-float rows).
// First matmul step folds the (1,1) init via 4-operand fma2n, so after the
// fused matmul acc[i] = (1 - l1_i, 1 - l2_i) = (u_i, v_i) directly.
// Then y_k = 1 - prod_{i+j=k} max(u_i, v_j); normalization fused as
// res_k = fma(-prod_k, inv, inv) with sum(res) = 19 - sum(prod).
__device__ __forceinline__ void compute_row(const float2 av[5], const float2 bv[5],
                                            const float (*sPtI)[24],
                                            float res[19]) {
    u64 acc[10];
    const u64 ONE2 = pack2(1.0f, 1.0f);

#pragma unroll
    for (int j = 0; j < 10; ++j) {
        float a = (j & 1) ? av[j >> 1].y : av[j >> 1].x;
        float b = (j & 1) ? bv[j >> 1].y : bv[j >> 1].x;
        u64 ab = pack2(a, b);                       // (p1_j, p2_j)
        const ulonglong2* r = (const ulonglong2*)&sPtI[j][0];
        ulonglong2 q0 = r[0], q1 = r[1], q2 = r[2], q3 = r[3], q4 = r[4];
        if (j == 0) {
            // init-fold: acc = ab * (-P col) + (1,1)
            acc[0] = fma2n(ab, q0.x, ONE2);
            acc[1] = fma2n(ab, q0.y, ONE2);
            acc[2] = fma2n(ab, q1.x, ONE2);
            acc[3] = fma2n(ab, q1.y, ONE2);
            acc[4] = fma2n(ab, q2.x, ONE2);
            acc[5] = fma2n(ab, q2.y, ONE2);
            acc[6] = fma2n(ab, q3.x, ONE2);
            acc[7] = fma2n(ab, q3.y, ONE2);
            acc[8] = fma2n(ab, q4.x, ONE2);
            acc[9] = fma2n(ab, q4.y, ONE2);
        } else {
            fma2(acc[0], ab, q0.x);
            fma2(acc[1], ab, q0.y);
            fma2(acc[2], ab, q1.x);
            fma2(acc[3], ab, q1.y);
            fma2(acc[4], ab, q2.x);
            fma2(acc[5], ab, q2.y);
            fma2(acc[6], ab, q3.x);
            fma2(acc[7], ab, q3.y);
            fma2(acc[8], ab, q4.x);
            fma2(acc[9], ab, q4.y);
        }
    }

    float u[10], v[10];
#pragma unroll
    for (int i = 0; i < 10; ++i) unpack2(acc[i], u[i], v[i]);

    // prod[k] = prod_{i+j=k} max(u_i, v_j)
    float prod[19];
#pragma unroll
    for (int j = 0; j < 10; ++j) prod[j] = fmaxf(u[0], v[j]);     // i = 0 row
#pragma unroll
    for (int i = 1; i < 10; ++i) prod[9 + i] = fmaxf(u[i], v[9]); // j = 9 col
#pragma unroll
    for (int i = 1; i < 10; ++i) {
#pragma unroll
        for (int j = 0; j < 9; ++j)
            prod[i + j] *= fmaxf(u[i], v[j]);
    }

    // sum(res) = 19 - sum(prod); res_k = (1 - prod_k) * inv = fma(-prod_k, inv, inv)
    float s0 = 0.f, s1 = 0.f, s2 = 0.f, s3 = 0.f;
#pragma unroll
    for (int k = 0; k < 19; ++k) {
        if ((k & 3) == 0) s0 += prod[k];
        else if ((k & 3) == 1) s1 += prod[k];
        else if ((k & 3) == 2) s2 += prod[k];
        else s3 += prod[k];
    }
    float sum = 19.0f - ((s0 + s1) + (s2 + s3));
    float inv = __fdividef(1.0f, sum + 1e-9f);
#pragma unroll
    for (int k = 0; k < 19; ++k) res[k] = fmaf(-prod[k], inv, inv);
}

__global__ __launch_bounds__(TILE, 4)
void bacon_kernel(const float* __restrict__ p1,
                  const float* __restrict__ p2,
                  const float* __restrict__ W1,
                  const float* __restrict__ W2,
                  float* __restrict__ out,
                  int B, int ntiles) {
    // per-warp private double-buffered staging slices (2 x 640 floats):
    // buffer = p1 rows [0,320) + p2 rows [320,640); reused for output staging.
    __shared__ __align__(16) float ws[WARPS][2][640];
    __shared__ __align__(16) float sPtI[10][24];   // interleaved NEGATED: [j][2i+m]

    const int tid  = threadIdx.x;
    const int lane = tid & 31;
    const int w    = tid >> 5;
    const int G    = gridDim.x;

    // Inline soft-perm prep: threads 0..19 (thread = matrix m, row r).
    if (tid < 20) {
        const float* W = (tid < 10) ? W1 : W2;
        int r = tid % 10, m = tid / 10;
        float row[10];
        float lo = 1e30f, hi = -1e30f;
#pragma unroll
        for (int j = 0; j < 10; ++j) {
            row[j] = W[r * 10 + j];
            lo = fminf(lo, row[j]);
            hi = fmaxf(hi, row[j]);
        }
        float invr = 1.0f / (hi - lo + 1e-8f);
        float s = 0.0f;
#pragma unroll
        for (int j = 0; j < 10; ++j) {
            row[j] = (row[j] - lo) * invr;
            s += row[j];
        }
        float invs = 1.0f / (s + 1e-8f);
#pragma unroll
        for (int j = 0; j < 10; ++j)
            sPtI[j][2 * r + m] = -(row[j] * invs);   // NEGATED interleaved store
    }
    __syncthreads();   // the only block barrier

    // stage this warp's 32-row slab of tile t into buffer buf (fast path only)
    auto stage = [&](int buf, int t) {
        const float4* g1 = (const float4*)p1 + (size_t)t * 640 + w * 80;
        const float4* g2 = (const float4*)p2 + (size_t)t * 640 + w * 80;
        float4* s = (float4*)ws[w][buf];
#pragma unroll
        for (int i = 0; i < 5; ++i) {
            int idx = lane + i * 32;
            const float4* src = (idx < 80) ? (g1 + idx) : (g2 + (idx - 80));
            cp_async16(&s[idx], src);
        }
    };

    int cur = blockIdx.x;
    if (cur >= ntiles) return;
    const bool cur_full0 = (cur * TILE + (w + 1) * 32 <= B);
    if (cur_full0) { stage(0, cur); cp_commit(); }

    int p = 0;
    for (; cur < ntiles; cur += G) {
        const int nxt = cur + G;
        const bool cur_full = (cur * TILE + (w + 1) * 32 <= B);
        const bool nxt_full = (nxt < ntiles) && (nxt * TILE + (w + 1) * 32 <= B);

        if (nxt_full) { stage(1 - p, nxt); cp_commit(); }

        if (cur_full) {
            if (nxt_full) cp_wait<1>(); else cp_wait<0>();
            __syncwarp();

            float* slice = ws[w][p];
            float2 av[5], bv[5];
#pragma unroll
            for (int jj = 0; jj < 5; ++jj) {
                av[jj] = *(const float2*)&slice[lane * 10 + jj * 2];
                bv[jj] = *(const float2*)&slice[320 + lane * 10 + jj * 2];
            }
            __syncwarp();   // input reads done before output staging overwrites

            float res[19];
            compute_row(av, bv, sPtI, res);

#pragma unroll
            for (int k = 0; k < 19; ++k) slice[lane * 19 + k] = res[k];  // stride 19: conflict-free
            __syncwarp();

            float4* og = (float4*)out + (size_t)cur * 1216 + w * 152;
            const float4* sv = (const float4*)slice;
#pragma unroll
            for (int i = 0; i < 5; ++i) {
                int idx = lane + i * 32;
                if (idx < 152) og[idx] = sv[idx];
            }
            __syncwarp();   // copy reads done before this buffer's next prefetch
        } else {
            // tail slab: scalar, no smem
            cp_wait<0>();
            int row = cur * TILE + w * 32 + lane;
            if (row < B) {
                float2 av[5], bv[5];
#pragma unroll
                for (int jj = 0; jj < 5; ++jj) {
                    av[jj] = *(const float2*)&p1[(size_t)row * 10 + jj * 2];
                    bv[jj] = *(const float2*)&p2[(size_t)row * 10 + jj * 2];
                }
                float res[19];
                compute_row(av, bv, sPtI, res);
#pragma unroll
                for (int k = 0; k < 19; ++k)
                    out[(size_t)row * 19 + k] = res[k];
            }
            __syncwarp();
        }
        p ^= 1;
    }
}

extern "C" void kernel_launch(void* const* d_in, const int* in_sizes, int n_in,
                              void* d_out, int out_size) {
    const float* p1 = (const float*)d_in[0];
    const float* p2 = (const float*)d_in[1];
    const float* W1 = (const float*)d_in[2];
    const float* W2 = (const float*)d_in[3];
    float* out = (float*)d_out;

    int B = in_sizes[0] / 10;
    int ntiles = (B + TILE - 1) / TILE;

    // one balanced wave at occupancy 4 on 148 SMs (~1% makespan tail)
    int G = 592;
    if (G > ntiles) G = ntiles;
    if (G < 1) G = 1;

    bacon_kernel<<<G, TILE>>>(p1, p2, W1, W2, out, B, ntiles);
}